// round 12
// baseline (speedup 1.0000x reference)
#include <cuda_runtime.h>

// LIF SNN scan: T=1024 timesteps, B*N = 65536 independent columns.
// out layout: [ spikes (T*BN) | v_final (BN) | i_final (BN) ]
// R12: R9 body (float2 rolling ring, plain __ldg/STG — best kernel 76.2us)
// with PF 32 -> 64: warp self-throttles at M_max~55 outstanding LDG.64
// (~97 KB/SM in flight, 3.8x latency knee) to probe DRAM queue depth.
// float2 occupancy is grid-capped (3.46 CTA/SM), so the register growth that
// sank R5 (float1 PF=64) cannot reduce occupancy here.

#define T_STEPS 1024
#define BN      65536
#define NCOL2   (BN / 2)    // float2 columns
#define PF      64

__global__ __launch_bounds__(64)
void snn_lif_kernel(const float2* __restrict__ x, float2* __restrict__ out) {
    const int idx = blockIdx.x * blockDim.x + threadIdx.x;  // float2-column id
    const float2* xp = x + idx;
    float2*       zp = out + idx;

    float v0 = 0.0f, v1 = 0.0f;     // membrane potentials
    float c0 = 0.0f, c1 = 0.0f;     // synaptic currents

    // prologue: fill the prefetch ring
    float2 xbuf[PF];
    #pragma unroll
    for (int j = 0; j < PF; ++j)
        xbuf[j] = __ldg(xp + (long)j * NCOL2);

    // dt*tau_mem_inv = 0.1, (1 - dt*tau_syn_inv) = 0.8, v_th = 1, v_reset = 0
    for (int t0 = 0; t0 < T_STEPS - PF; t0 += PF) {
        #pragma unroll
        for (int j = 0; j < PF; ++j) {
            const float2 xt = xbuf[j];
            // immediately re-issue this slot for t0+PF+j (ring stays full)
            xbuf[j] = __ldg(xp + (long)(t0 + PF + j) * NCOL2);

            float2 z;

            const float vd0 = fmaf(0.1f, c0 - v0, v0);
            const bool  f0  = (vd0 > 1.0f);
            z.x = f0 ? 1.0f : 0.0f;
            v0  = f0 ? 0.0f : vd0;
            c0  = fmaf(c0, 0.8f, xt.x);

            const float vd1 = fmaf(0.1f, c1 - v1, v1);
            const bool  f1  = (vd1 > 1.0f);
            z.y = f1 ? 1.0f : 0.0f;
            v1  = f1 ? 0.0f : vd1;
            c1  = fmaf(c1, 0.8f, xt.y);

            zp[(long)(t0 + j) * NCOL2] = z;
        }
    }

    // epilogue: last PF steps, no prefetch
    #pragma unroll
    for (int j = 0; j < PF; ++j) {
        const float2 xt = xbuf[j];

        float2 z;

        const float vd0 = fmaf(0.1f, c0 - v0, v0);
        const bool  f0  = (vd0 > 1.0f);
        z.x = f0 ? 1.0f : 0.0f;
        v0  = f0 ? 0.0f : vd0;
        c0  = fmaf(c0, 0.8f, xt.x);

        const float vd1 = fmaf(0.1f, c1 - v1, v1);
        const bool  f1  = (vd1 > 1.0f);
        z.y = f1 ? 1.0f : 0.0f;
        v1  = f1 ? 0.0f : vd1;
        c1  = fmaf(c1, 0.8f, xt.y);

        zp[(long)(T_STEPS - PF + j) * NCOL2] = z;
    }

    // final state after the full scan: v then i, each BN floats (NCOL2 float2)
    float2 vf; vf.x = v0; vf.y = v1;
    float2 cf; cf.x = c0; cf.y = c1;
    out[(long)T_STEPS * NCOL2 + idx]          = vf;
    out[(long)T_STEPS * NCOL2 + NCOL2 + idx]  = cf;
}

extern "C" void kernel_launch(void* const* d_in, const int* in_sizes, int n_in,
                              void* d_out, int out_size) {
    const float2* x   = (const float2*)d_in[0];
    float2*       out = (float2*)d_out;
    (void)in_sizes; (void)n_in; (void)out_size;

    snn_lif_kernel<<<NCOL2 / 64, 64>>>(x, out);
}

// round 13
// speedup vs baseline: 1.0937x; 1.0937x over previous
#include <cuda_runtime.h>

// LIF SNN scan: T=1024 timesteps, B*N = 65536 independent columns.
// out layout: [ spikes (T*BN) | v_final (BN) | i_final (BN) ]
// FINAL (== R9): float2 columns, rolling software-prefetch ring PF=32.
// Converged optimum: depth {16,32,64} peaks at 32 (under the ~55/warp LSU
// accept cap; deeper hard-stalls the warp and starves the store stream),
// width {f1,f2,f4} peaks at f2 (LSU relief vs warp-count tradeoff), phase
// batching / cache hints / wave rebalancing all regress. 6.36 TB/s = 80% of
// HBM spec on a 50/50 R/W mix with 512 MB mandatory traffic — controller-side
// ceiling, not software-visible.

#define T_STEPS 1024
#define BN      65536
#define NCOL2   (BN / 2)    // float2 columns
#define PF      32

__global__ __launch_bounds__(64, 4)
void snn_lif_kernel(const float2* __restrict__ x, float2* __restrict__ out) {
    const int idx = blockIdx.x * blockDim.x + threadIdx.x;  // float2-column id
    const float2* xp = x + idx;
    float2*       zp = out + idx;

    float v0 = 0.0f, v1 = 0.0f;     // membrane potentials
    float c0 = 0.0f, c1 = 0.0f;     // synaptic currents

    // prologue: fill the prefetch ring (32 independent LDG.64 in flight)
    float2 xbuf[PF];
    #pragma unroll
    for (int j = 0; j < PF; ++j)
        xbuf[j] = __ldg(xp + (long)j * NCOL2);

    // dt*tau_mem_inv = 0.1, (1 - dt*tau_syn_inv) = 0.8, v_th = 1, v_reset = 0
    for (int t0 = 0; t0 < T_STEPS - PF; t0 += PF) {
        #pragma unroll
        for (int j = 0; j < PF; ++j) {
            const float2 xt = xbuf[j];
            // immediately re-issue this slot for t0+PF+j (ring stays full)
            xbuf[j] = __ldg(xp + (long)(t0 + PF + j) * NCOL2);

            float2 z;

            const float vd0 = fmaf(0.1f, c0 - v0, v0);
            const bool  f0  = (vd0 > 1.0f);
            z.x = f0 ? 1.0f : 0.0f;
            v0  = f0 ? 0.0f : vd0;
            c0  = fmaf(c0, 0.8f, xt.x);

            const float vd1 = fmaf(0.1f, c1 - v1, v1);
            const bool  f1  = (vd1 > 1.0f);
            z.y = f1 ? 1.0f : 0.0f;
            v1  = f1 ? 0.0f : vd1;
            c1  = fmaf(c1, 0.8f, xt.y);

            zp[(long)(t0 + j) * NCOL2] = z;
        }
    }

    // epilogue: last PF steps, no prefetch
    #pragma unroll
    for (int j = 0; j < PF; ++j) {
        const float2 xt = xbuf[j];

        float2 z;

        const float vd0 = fmaf(0.1f, c0 - v0, v0);
        const bool  f0  = (vd0 > 1.0f);
        z.x = f0 ? 1.0f : 0.0f;
        v0  = f0 ? 0.0f : vd0;
        c0  = fmaf(c0, 0.8f, xt.x);

        const float vd1 = fmaf(0.1f, c1 - v1, v1);
        const bool  f1  = (vd1 > 1.0f);
        z.y = f1 ? 1.0f : 0.0f;
        v1  = f1 ? 0.0f : vd1;
        c1  = fmaf(c1, 0.8f, xt.y);

        zp[(long)(T_STEPS - PF + j) * NCOL2] = z;
    }

    // final state after the full scan: v then i, each BN floats (NCOL2 float2)
    float2 vf; vf.x = v0; vf.y = v1;
    float2 cf; cf.x = c0; cf.y = c1;
    out[(long)T_STEPS * NCOL2 + idx]          = vf;
    out[(long)T_STEPS * NCOL2 + NCOL2 + idx]  = cf;
}

extern "C" void kernel_launch(void* const* d_in, const int* in_sizes, int n_in,
                              void* d_out, int out_size) {
    const float2* x   = (const float2*)d_in[0];
    float2*       out = (float2*)d_out;
    (void)in_sizes; (void)n_in; (void)out_size;

    snn_lif_kernel<<<NCOL2 / 64, 64>>>(x, out);
}